// round 1
// baseline (speedup 1.0000x reference)
#include <cuda_runtime.h>
#include <math.h>

#define MAXN 100000
#define MAXE 3200000
#define H 64

// ---------------- scratch (static device memory; no allocations) ----------------
__device__ int      g_is64;
__device__ unsigned g_deg[MAXN];
__device__ float    g_dinv[MAXN];
__device__ float    g_s[MAXN];
__device__ float    g_z[MAXN];
__device__ float    g_o[MAXN];
__device__ __align__(16) float g_h[(size_t)MAXN * H];    // g = relu(s*W0+b0) @ W1
__device__ __align__(16) float g_agg[(size_t)MAXN * H];  // layer-2 aggregation
__device__ int      g_r32[MAXE];
__device__ int      g_c32[MAXE];
__device__ float    g_norm[MAXE];

// ---------------- dtype detection: int64 vs int32 edge_index ----------------
__global__ void k_detect(const int* ei32) {
    __shared__ int any_nonzero;
    if (threadIdx.x == 0) any_nonzero = 0;
    __syncthreads();
    int a = 0;
    // If data is int64 (values < 2^31, nonneg), every odd 32-bit word is 0.
    // If data is int32 random in [0, 1e5), odd words are almost surely nonzero.
    for (int i = threadIdx.x; i < 4096; i += blockDim.x)
        if (ei32[2 * i + 1] != 0) a = 1;
    if (a) any_nonzero = 1;
    __syncthreads();
    if (threadIdx.x == 0) g_is64 = (any_nonzero == 0) ? 1 : 0;
}

// ---------------- init degree with self-loop ----------------
__global__ void k_init_deg(int n) {
    int i = blockIdx.x * blockDim.x + threadIdx.x;
    if (i < n) g_deg[i] = 1u;
}

// ---------------- decode edges to int32 + degree count ----------------
__global__ void k_deg(const void* ei, int E) {
    int e = blockIdx.x * blockDim.x + threadIdx.x;
    if (e >= E) return;
    int r, c;
    if (g_is64) {
        const long long* p = (const long long*)ei;
        r = (int)p[e];
        c = (int)p[e + E];
    } else {
        const int* p = (const int*)ei;
        r = p[e];
        c = p[e + E];
    }
    g_r32[e] = r;
    g_c32[e] = c;
    atomicAdd(&g_deg[c], 1u);
}

// ---------------- dinv + init s with self-loop term ----------------
__global__ void k_dinv(const float* __restrict__ x, int n) {
    int i = blockIdx.x * blockDim.x + threadIdx.x;
    if (i >= n) return;
    float d = rsqrtf((float)g_deg[i]);   // deg >= 1 always
    g_dinv[i] = d;
    g_s[i] = d * d * x[i];               // self-loop contribution to scalar SpMV
}

// ---------------- norm per edge + scalar SpMV for layer 0 ----------------
__global__ void k_norm_spmv0(const float* __restrict__ x, int E) {
    int e = blockIdx.x * blockDim.x + threadIdx.x;
    if (e >= E) return;
    int r = g_r32[e], c = g_c32[e];
    float nm = g_dinv[r] * g_dinv[c];
    g_norm[e] = nm;
    atomicAdd(&g_s[c], nm * x[r]);
}

// ---------------- dense: g[i,:] = relu(s[i]*W0 + b0) @ W1 ; agg init with self-loop ----------------
__global__ __launch_bounds__(256) void k_dense(const float* __restrict__ W0,
                                               const float* __restrict__ b0,
                                               const float* __restrict__ W1,
                                               int n) {
    __shared__ float h_sh[4][H];
    const int j = threadIdx.x & 63;      // output feature
    const int grp = threadIdx.x >> 6;    // node group within block (4 nodes/block/iter)

    // W1 column j in registers (reused across all nodes this block touches)
    float w[H];
#pragma unroll
    for (int k = 0; k < H; k++) w[k] = __ldg(&W1[k * H + j]);
    const float w0j = __ldg(&W0[j]);
    const float b0j = __ldg(&b0[j]);

    const int stride = gridDim.x * 4;
    const int trips = (n + stride - 1) / stride;
    int node = blockIdx.x * 4 + grp;
    for (int it = 0; it < trips; ++it, node += stride) {
        const bool active = (node < n);
        float sv = 0.f, d2 = 0.f;
        if (active) {
            sv = g_s[node];
            float d = g_dinv[node];
            d2 = d * d;
        }
        // thread j doubles as "k" for computing h[k]
        h_sh[grp][j] = fmaxf(sv * w0j + b0j, 0.f);
        __syncthreads();
        float acc = 0.f;
#pragma unroll
        for (int k = 0; k < H; k++) acc = fmaf(h_sh[grp][k], w[k], acc);
        if (active) {
            g_h[(size_t)node * H + j] = acc;
            g_agg[(size_t)node * H + j] = d2 * acc;   // self-loop init
        }
        __syncthreads();
    }
}

// ---------------- big SpMM: agg[c,:] += norm * g[r,:] (16 lanes/edge, float4 + red.v4) ----------------
__global__ __launch_bounds__(256) void k_spmm(int E) {
    long long t = (long long)blockIdx.x * blockDim.x + threadIdx.x;
    long long e = t >> 4;
    int lane = (int)(t & 15);
    if (e >= E) return;
    int r = g_r32[e];
    int c = g_c32[e];
    float nm = g_norm[e];
    const float4* src = (const float4*)g_h;
    float4 v = src[(long long)r * 16 + lane];
    float4* dst = ((float4*)g_agg) + (long long)c * 16 + lane;
    unsigned long long gaddr = (unsigned long long)__cvta_generic_to_global((void*)dst);
    asm volatile("red.global.add.v4.f32 [%0], {%1,%2,%3,%4};"
                 :: "l"(gaddr), "f"(nm * v.x), "f"(nm * v.y), "f"(nm * v.z), "f"(nm * v.w)
                 : "memory");
}

// ---------------- z[i] = relu(agg[i]+b1) . W_out ; init o with self-loop ----------------
__global__ void k_zdot(const float* __restrict__ b1, const float* __restrict__ Wout, int n) {
    int gt = blockIdx.x * blockDim.x + threadIdx.x;
    int node = gt >> 5;
    int lane = gt & 31;
    if (node >= n) return;
    const float2* a2 = (const float2*)g_agg;
    float2 a = a2[(size_t)node * 32 + lane];
    float v0 = fmaxf(a.x + __ldg(&b1[2 * lane]), 0.f);
    float v1 = fmaxf(a.y + __ldg(&b1[2 * lane + 1]), 0.f);
    float acc = v0 * __ldg(&Wout[2 * lane]) + v1 * __ldg(&Wout[2 * lane + 1]);
#pragma unroll
    for (int o = 16; o > 0; o >>= 1) acc += __shfl_down_sync(0xffffffffu, acc, o);
    if (lane == 0) {
        g_z[node] = acc;
        float d = g_dinv[node];
        g_o[node] = d * d * acc;
    }
}

// ---------------- scalar SpMV for output layer ----------------
__global__ void k_spmv2(int E) {
    int e = blockIdx.x * blockDim.x + threadIdx.x;
    if (e >= E) return;
    atomicAdd(&g_o[g_c32[e]], g_norm[e] * g_z[g_r32[e]]);
}

// ---------------- sigmoid epilogue ----------------
__global__ void k_final(const float* __restrict__ bout, float* __restrict__ out, int n) {
    int i = blockIdx.x * blockDim.x + threadIdx.x;
    if (i >= n) return;
    float v = g_o[i] + __ldg(&bout[0]);
    out[i] = 1.f / (1.f + expf(-v));
}

// ---------------- launch ----------------
extern "C" void kernel_launch(void* const* d_in, const int* in_sizes, int n_in,
                              void* d_out, int out_size) {
    const float* x    = (const float*)d_in[0];
    const void*  ei   = d_in[1];
    const float* W0   = (const float*)d_in[2];
    const float* b0   = (const float*)d_in[3];
    const float* W1   = (const float*)d_in[4];
    const float* b1   = (const float*)d_in[5];
    const float* Wout = (const float*)d_in[6];
    const float* bout = (const float*)d_in[7];

    int n = in_sizes[0];
    int E = in_sizes[1] / 2;
    if (n > MAXN) n = MAXN;
    if (E > MAXE) E = MAXE;

    const int TB = 256;
    int gN = (n + TB - 1) / TB;
    int gE = (E + TB - 1) / TB;

    k_detect<<<1, 256>>>((const int*)ei);
    k_init_deg<<<gN, TB>>>(n);
    k_deg<<<gE, TB>>>(ei, E);
    k_dinv<<<gN, TB>>>(x, n);
    k_norm_spmv0<<<gE, TB>>>(x, E);

    // dense: 4 nodes per block, ~16 trips per block
    int dense_grid = (n + 4 * 16 - 1) / (4 * 16);
    k_dense<<<dense_grid, 256>>>(W0, b0, W1, n);

    // SpMM: 16 lanes per edge
    long long spmm_threads = (long long)E * 16;
    int spmm_grid = (int)((spmm_threads + TB - 1) / TB);
    k_spmm<<<spmm_grid, TB>>>(E);

    int zdot_grid = (int)(((long long)n * 32 + TB - 1) / TB);
    k_zdot<<<zdot_grid, TB>>>(b1, Wout, n);

    k_spmv2<<<gE, TB>>>(E);
    k_final<<<gN, TB>>>(bout, (float*)d_out, n);
}